// round 8
// baseline (speedup 1.0000x reference)
#include <cuda_runtime.h>

#define NUM_CLASSES 1000
#define FEAT_DIM 512
#define BATCH 65536
#define NSLAB 32
#define HIST_THREADS 1024
#define SCAT_THREADS 256
#define THREADS 512
#define WARPS_PER_BLOCK (THREADS / 32)      // 16
#define NBLOCKS (BATCH / WARPS_PER_BLOCK)   // 4096

// Scratch. g_part/g_off/g_winv/g_sorted are fully overwritten every call.
// g_ticket is reset by the last hist block each call (zero at module load).
__device__ int g_part[NUM_CLASSES * NSLAB];
__device__ int g_off[NUM_CLASSES * NSLAB];
__device__ float g_winv[NUM_CLASSES];
__device__ unsigned int g_sorted[BATCH];
__device__ unsigned int g_ticket;

// K1: per-slab histograms; last block (32-way ticket) scans into scatter
// offsets + per-class weights, zeroes out[0], resets the ticket.
__global__ void __launch_bounds__(HIST_THREADS) cl_hist_scan_kernel(
    const long long* __restrict__ labels,
    float* __restrict__ out)
{
    __shared__ int h[NUM_CLASSES];
    __shared__ int s_scan[HIST_THREADS];
    __shared__ unsigned int s_ticket;

    int tid = threadIdx.x;
    for (int c = tid; c < NUM_CLASSES; c += HIST_THREADS) h[c] = 0;
    __syncthreads();

    // 2048 labels per block; 2 per thread via one longlong2.
    const longlong2* lab2 =
        reinterpret_cast<const longlong2*>(labels + (size_t)blockIdx.x * (BATCH / NSLAB));
    longlong2 v = lab2[tid];
    atomicAdd(&h[(int)v.x], 1);
    atomicAdd(&h[(int)v.y], 1);
    __syncthreads();

    int b = blockIdx.x;
    for (int c = tid; c < NUM_CLASSES; c += HIST_THREADS)
        g_part[c * NSLAB + b] = h[c];

    // ---- 32-block ticket; last block performs the scan ----
    __syncthreads();
    if (tid == 0) {
        __threadfence();
        s_ticket = atomicAdd(&g_ticket, 1u);
    }
    __syncthreads();
    if (s_ticket != NSLAB - 1) return;

    // Last block: per-class totals (sum of 32 slab partials).
    int tot = 0;
    if (tid < NUM_CLASSES) {
#pragma unroll
        for (int s = 0; s < NSLAB; s++)
            tot += g_part[tid * NSLAB + s];  // L2-coherent after fences+ticket
    }
    s_scan[tid] = tot;
    __syncthreads();

    // Hillis-Steele inclusive scan over 1024 (1000 used) entries.
#pragma unroll
    for (int o = 1; o < HIST_THREADS; o <<= 1) {
        int add = (tid >= o) ? s_scan[tid - o] : 0;
        __syncthreads();
        s_scan[tid] += add;
        __syncthreads();
    }

    if (tid < NUM_CLASSES) {
        int running = s_scan[tid] - tot;  // exclusive class start
#pragma unroll
        for (int s = 0; s < NSLAB; s++) {
            g_off[tid * NSLAB + s] = running;
            running += g_part[tid * NSLAB + s];
        }
        g_winv[tid] = (tot > 0)
            ? 1.0f / ((float)tot * (float)FEAT_DIM) * (1.0f / (float)BATCH)
            : 0.0f;
    }
    if (tid == 0) {
        out[0] = 0.0f;
        g_ticket = 0u;  // reset for next graph replay
    }
}

// K2: scatter rows into label-sorted order. Per-warp duplicate ranking via
// match_any; smem cursors seeded from g_off -> no global atomics.
__global__ void __launch_bounds__(SCAT_THREADS) cl_scatter_kernel(
    const long long* __restrict__ labels)
{
    __shared__ int cursor[NUM_CLASSES];
    int tid = threadIdx.x;
    int lane = tid & 31;
    int b = blockIdx.x;

    for (int c = tid; c < NUM_CLASSES; c += SCAT_THREADS)
        cursor[c] = g_off[c * NSLAB + b];
    __syncthreads();

    int base_row = b * (BATCH / NSLAB);
#pragma unroll
    for (int it = 0; it < (BATCH / NSLAB) / SCAT_THREADS; it++) {
        int idx = base_row + it * SCAT_THREADS + tid;
        int lab = (int)labels[idx];

        unsigned int mask = __match_any_sync(0xffffffffu, lab);
        int leader = __ffs(mask) - 1;
        int grp = __popc(mask);
        int rank = __popc(mask & ((1u << lane) - 1u));

        int pos = 0;
        if (lane == leader)
            pos = atomicAdd(&cursor[lab], grp);
        pos = __shfl_sync(0xffffffffu, pos, leader);

        g_sorted[pos + rank] = ((unsigned int)lab << 16) | (unsigned int)idx;
    }
}

// K3: one warp per sorted row. Adjacent warps share labels -> center rows and
// weights are L1-hot. Streaming feature loads; one atomicAdd(out) per block.
__global__ void __launch_bounds__(THREADS) cl_main_kernel(
    const float* __restrict__ features,
    const float* __restrict__ centers,
    float* __restrict__ out)
{
    __shared__ float red[WARPS_PER_BLOCK];

    int warp = threadIdx.x >> 5;
    int lane = threadIdx.x & 31;

    unsigned int packed = __ldg(&g_sorted[blockIdx.x * WARPS_PER_BLOCK + warp]);
    int lab = (int)(packed >> 16);
    int row = (int)(packed & 0xFFFFu);

    const float4* frow = reinterpret_cast<const float4*>(features + (size_t)row * FEAT_DIM);
    const float4* crow = reinterpret_cast<const float4*>(centers + (size_t)lab * FEAT_DIM);

    float acc = 0.0f;
#pragma unroll
    for (int i = 0; i < 4; i++) {
        float4 a = __ldcs(frow + lane + i * 32);  // evict-first stream
        float4 b = __ldg(crow + lane + i * 32);   // L1-hot (shared across warps)
        float dx = a.x - b.x;
        float dy = a.y - b.y;
        float dz = a.z - b.z;
        float dw = a.w - b.w;
        acc += dx * dx + dy * dy + dz * dz + dw * dw;
    }

#pragma unroll
    for (int o = 16; o; o >>= 1)
        acc += __shfl_xor_sync(0xffffffffu, acc, o);

    if (lane == 0)
        red[warp] = acc * __ldg(&g_winv[lab]);
    __syncthreads();

    if (warp == 0) {
        float v = (lane < WARPS_PER_BLOCK) ? red[lane] : 0.0f;
#pragma unroll
        for (int o = 8; o; o >>= 1)
            v += __shfl_xor_sync(0xffffffffu, v, o);
        if (lane == 0)
            atomicAdd(out, v);
    }
}

extern "C" void kernel_launch(void* const* d_in, const int* in_sizes, int n_in,
                              void* d_out, int out_size) {
    const float* features = (const float*)d_in[0];
    const float* centers = (const float*)d_in[1];
    const long long* labels = (const long long*)d_in[2];
    float* out = (float*)d_out;

    cl_hist_scan_kernel<<<NSLAB, HIST_THREADS>>>(labels, out);
    cl_scatter_kernel<<<NSLAB, SCAT_THREADS>>>(labels);
    cl_main_kernel<<<NBLOCKS, THREADS>>>(features, centers, out);
}

// round 9
// speedup vs baseline: 3.2071x; 3.2071x over previous
#include <cuda_runtime.h>

#define NUM_CLASSES 1000
#define FEAT_DIM 512
#define BATCH 65536
#define NSLAB 32
#define HIST_THREADS 256
#define THREADS 512
#define WARPS_PER_BLOCK (THREADS / 32)          // 16
#define MAIN_BLOCKS 592                          // 148 SMs * 4 blocks
#define TOTAL_WARPS (MAIN_BLOCKS * WARPS_PER_BLOCK)  // 9472
// 1 / (FEAT_DIM * BATCH) = 2^-25, exact
#define INV_FD_BATCH (1.0f / 33554432.0f)

// Per-block partial histograms, transposed: g_part[class][slab].
// Fully overwritten by K1 every call -> no reset, no atomics, deterministic.
__device__ int g_part[NUM_CLASSES * NSLAB];

// K1: 32 blocks; each builds a private smem histogram of its 2048 labels and
// stores it into its slab column with plain STGs. Block 0 zeroes out[0].
__global__ void __launch_bounds__(HIST_THREADS) cl_hist_kernel(
    const long long* __restrict__ labels,
    float* __restrict__ out)
{
    __shared__ int h[NUM_CLASSES];
    for (int c = threadIdx.x; c < NUM_CLASSES; c += HIST_THREADS) h[c] = 0;
    if (blockIdx.x == 0 && threadIdx.x == 0) out[0] = 0.0f;
    __syncthreads();

    const longlong2* lab2 =
        reinterpret_cast<const longlong2*>(labels + (size_t)blockIdx.x * (BATCH / NSLAB));
#pragma unroll
    for (int i = 0; i < 4; i++) {
        longlong2 v = lab2[threadIdx.x * 4 + i];
        atomicAdd(&h[(int)v.x], 1);
        atomicAdd(&h[(int)v.y], 1);
    }
    __syncthreads();

    int b = blockIdx.x;
    for (int c = threadIdx.x; c < NUM_CLASSES; c += HIST_THREADS)
        g_part[c * NSLAB + b] = h[c];
}

// K2: persistent grid-stride main. One warp walks rows with stride 9472.
// Per row: 4 streaming feature float4s + 4 cached center float4s, count via
// one REDUX over the L1-hot slab line, weight applied per-lane; ALL reduction
// deferred to a single per-block epilogue + one un-fenced atomicAdd(out).
__global__ void __launch_bounds__(THREADS, 4) cl_main_kernel(
    const float* __restrict__ features,
    const float* __restrict__ centers,
    const long long* __restrict__ labels,
    float* __restrict__ out)
{
    __shared__ float red[WARPS_PER_BLOCK];

    int warp = threadIdx.x >> 5;
    int lane = threadIdx.x & 31;
    int gw = blockIdx.x * WARPS_PER_BLOCK + warp;

    float total = 0.0f;

    for (int row = gw; row < BATCH; row += TOTAL_WARPS) {
        int lab = (int)labels[row];  // warp-uniform broadcast load

        int cnt = __reduce_add_sync(0xffffffffu, __ldg(&g_part[lab * NSLAB + lane]));

        const float4* frow = reinterpret_cast<const float4*>(features + (size_t)row * FEAT_DIM);
        const float4* crow = reinterpret_cast<const float4*>(centers + (size_t)lab * FEAT_DIM);

        float acc = 0.0f;
#pragma unroll
        for (int i = 0; i < 4; i++) {
            float4 a = __ldcs(frow + lane + i * 32);  // evict-first stream
            float4 b = __ldg(crow + lane + i * 32);   // cached: centers L2-resident
            float dx = a.x - b.x;
            float dy = a.y - b.y;
            float dz = a.z - b.z;
            float dw = a.w - b.w;
            acc += dx * dx + dy * dy + dz * dz + dw * dw;
        }

        total += acc * __fdividef(1.0f, (float)cnt);  // *2^-25 factored out below
    }

    // One reduction per block, not per row.
#pragma unroll
    for (int o = 16; o; o >>= 1)
        total += __shfl_xor_sync(0xffffffffu, total, o);
    if (lane == 0) red[warp] = total;
    __syncthreads();

    if (warp == 0) {
        float v = (lane < WARPS_PER_BLOCK) ? red[lane] : 0.0f;
#pragma unroll
        for (int o = 8; o; o >>= 1)
            v += __shfl_xor_sync(0xffffffffu, v, o);
        if (lane == 0)
            atomicAdd(out, v * INV_FD_BATCH);
    }
}

extern "C" void kernel_launch(void* const* d_in, const int* in_sizes, int n_in,
                              void* d_out, int out_size) {
    const float* features = (const float*)d_in[0];
    const float* centers = (const float*)d_in[1];
    const long long* labels = (const long long*)d_in[2];
    float* out = (float*)d_out;

    cl_hist_kernel<<<NSLAB, HIST_THREADS>>>(labels, out);
    cl_main_kernel<<<MAIN_BLOCKS, THREADS>>>(features, centers, labels, out);
}

// round 10
// speedup vs baseline: 3.2214x; 1.0044x over previous
#include <cuda_runtime.h>
#include <cstdint>

#define NUM_CLASSES 1000
#define FEAT_DIM 512
#define BATCH 65536
#define NSLAB 32
#define HIST_THREADS 256
#define THREADS 512
#define WARPS_PER_BLOCK 16
#define MAIN_BLOCKS 296                 // 2 blocks per SM
#define CHUNK_ROWS 16                   // one row per warp per chunk
#define ROW_BYTES (FEAT_DIM * 4)        // 2048
#define CHUNK_BYTES (CHUNK_ROWS * ROW_BYTES)  // 32768
#define NSTAGES 3                       // 96KB smem ring
#define NCHUNKS (BATCH / CHUNK_ROWS)    // 4096
#define INV_FD_BATCH (1.0f / 33554432.0f)  // 1/(512*65536), exact

// Per-block partial histograms, transposed: g_part[class][slab].
// Fully overwritten by K1 every call -> no reset, no atomics, deterministic.
__device__ int g_part[NUM_CLASSES * NSLAB];

// K1: 32 blocks; private smem histograms -> slab columns. Zeroes out[0].
__global__ void __launch_bounds__(HIST_THREADS) cl_hist_kernel(
    const long long* __restrict__ labels,
    float* __restrict__ out)
{
    __shared__ int h[NUM_CLASSES];
    for (int c = threadIdx.x; c < NUM_CLASSES; c += HIST_THREADS) h[c] = 0;
    if (blockIdx.x == 0 && threadIdx.x == 0) out[0] = 0.0f;
    __syncthreads();

    const longlong2* lab2 =
        reinterpret_cast<const longlong2*>(labels + (size_t)blockIdx.x * (BATCH / NSLAB));
#pragma unroll
    for (int i = 0; i < 4; i++) {
        longlong2 v = lab2[threadIdx.x * 4 + i];
        atomicAdd(&h[(int)v.x], 1);
        atomicAdd(&h[(int)v.y], 1);
    }
    __syncthreads();

    int b = blockIdx.x;
    for (int c = threadIdx.x; c < NUM_CLASSES; c += HIST_THREADS)
        g_part[c * NSLAB + b] = h[c];
}

// ---- minimal PTX wrappers ----
__device__ __forceinline__ uint32_t s2u(const void* p) {
    uint32_t a;
    asm("{ .reg .u64 t; cvta.to.shared.u64 t, %1; cvt.u32.u64 %0, t; }" : "=r"(a) : "l"(p));
    return a;
}
__device__ __forceinline__ void mbar_init(uint32_t mbar, uint32_t cnt) {
    asm volatile("mbarrier.init.shared.b64 [%0], %1;" :: "r"(mbar), "r"(cnt) : "memory");
}
__device__ __forceinline__ void mbar_expect_tx(uint32_t mbar, uint32_t bytes) {
    asm volatile("mbarrier.arrive.expect_tx.shared.b64 _, [%0], %1;" :: "r"(mbar), "r"(bytes) : "memory");
}
__device__ __forceinline__ void mbar_wait(uint32_t mbar, uint32_t parity) {
    uint32_t done;
    asm volatile(
        "{\n\t.reg .pred p;\n\t"
        "mbarrier.try_wait.parity.acquire.cta.shared::cta.b64 p, [%1], %2;\n\t"
        "selp.b32 %0, 1, 0, p;\n\t}"
        : "=r"(done) : "r"(mbar), "r"(parity) : "memory");
    if (!done) {
        asm volatile(
            "{\n\t.reg .pred P1;\n\t"
            "WL_%=:\n\t"
            "mbarrier.try_wait.parity.acquire.cta.shared::cta.b64 P1, [%0], %1, 0x989680;\n\t"
            "@P1 bra.uni WD_%=;\n\t"
            "bra.uni WL_%=;\n\t"
            "WD_%=:\n\t}"
            :: "r"(mbar), "r"(parity) : "memory");
    }
}
__device__ __forceinline__ void bulk_copy(uint32_t dst, const void* src,
                                          uint32_t bytes, uint32_t mbar, uint64_t pol) {
    asm volatile(
        "cp.async.bulk.shared::cluster.global.mbarrier::complete_tx::bytes.L2::cache_hint "
        "[%0], [%1], %2, [%3], %4;"
        :: "r"(dst), "l"(src), "r"(bytes), "r"(mbar), "l"(pol) : "memory");
}

// K2: persistent TMA-pipelined main. 3-stage smem ring of 16-row feature
// chunks; producer (tid 0) keeps 3 chunks in flight with evict_first L2
// policy. Consumers prefetch label/count/center into registers BEFORE the
// barrier wait, so the post-wait body is pure LDS+FFMA.
__global__ void __launch_bounds__(THREADS, 2) cl_main_kernel(
    const float* __restrict__ features,
    const float* __restrict__ centers,
    const long long* __restrict__ labels,
    float* __restrict__ out)
{
    extern __shared__ __align__(128) unsigned char sbuf[];  // NSTAGES * CHUNK_BYTES
    __shared__ __align__(8) unsigned long long mbar_full[NSTAGES];
    __shared__ float red[WARPS_PER_BLOCK];

    int tid = threadIdx.x;
    int warp = tid >> 5;
    int lane = tid & 31;

    uint32_t sb = s2u(sbuf);
    uint32_t fb = s2u(&mbar_full[0]);

    uint64_t pol;
    asm("createpolicy.fractional.L2::evict_first.b64 %0, 1.0;" : "=l"(pol));

    if (tid == 0) {
#pragma unroll
        for (int s = 0; s < NSTAGES; s++)
            mbar_init(fb + s * 8, 1);
    }
    __syncthreads();

    // Prologue: fill the ring.
    if (tid == 0) {
#pragma unroll
        for (int p = 0; p < NSTAGES; p++) {
            int chunk = blockIdx.x + p * MAIN_BLOCKS;
            if (chunk < NCHUNKS) {
                mbar_expect_tx(fb + p * 8, CHUNK_BYTES);
                bulk_copy(sb + p * CHUNK_BYTES,
                          features + (size_t)chunk * CHUNK_ROWS * FEAT_DIM,
                          CHUNK_BYTES, fb + p * 8, pol);
            }
        }
    }

    float total = 0.0f;
    int stage = 0;
    uint32_t parity = 0;

    for (int chunk = blockIdx.x; chunk < NCHUNKS; chunk += MAIN_BLOCKS) {
        int row = chunk * CHUNK_ROWS + warp;

        // Prefetch everything independent of the smem stage.
        int lab = (int)labels[row];
        int cnt = __reduce_add_sync(0xffffffffu, __ldg(&g_part[lab * NSLAB + lane]));
        const float4* crow = reinterpret_cast<const float4*>(centers + (size_t)lab * FEAT_DIM);
        float4 cb0 = __ldg(crow + lane);
        float4 cb1 = __ldg(crow + lane + 32);
        float4 cb2 = __ldg(crow + lane + 64);
        float4 cb3 = __ldg(crow + lane + 96);

        mbar_wait(fb + stage * 8, parity);

        const float4* srow = reinterpret_cast<const float4*>(
            sbuf + stage * CHUNK_BYTES + warp * ROW_BYTES);
        float4 a0 = srow[lane];
        float4 a1 = srow[lane + 32];
        float4 a2 = srow[lane + 64];
        float4 a3 = srow[lane + 96];

        float acc;
        {
            float dx = a0.x - cb0.x, dy = a0.y - cb0.y, dz = a0.z - cb0.z, dw = a0.w - cb0.w;
            acc = dx * dx + dy * dy + dz * dz + dw * dw;
        }
        {
            float dx = a1.x - cb1.x, dy = a1.y - cb1.y, dz = a1.z - cb1.z, dw = a1.w - cb1.w;
            acc += dx * dx + dy * dy + dz * dz + dw * dw;
        }
        {
            float dx = a2.x - cb2.x, dy = a2.y - cb2.y, dz = a2.z - cb2.z, dw = a2.w - cb2.w;
            acc += dx * dx + dy * dy + dz * dz + dw * dw;
        }
        {
            float dx = a3.x - cb3.x, dy = a3.y - cb3.y, dz = a3.z - cb3.z, dw = a3.w - cb3.w;
            acc += dx * dx + dy * dy + dz * dz + dw * dw;
        }

        total += acc * __fdividef(1.0f, (float)cnt);

        // All warps done with this stage -> producer refills it.
        __syncthreads();
        if (tid == 0) {
            int nchunk = chunk + NSTAGES * MAIN_BLOCKS;
            if (nchunk < NCHUNKS) {
                mbar_expect_tx(fb + stage * 8, CHUNK_BYTES);
                bulk_copy(sb + stage * CHUNK_BYTES,
                          features + (size_t)nchunk * CHUNK_ROWS * FEAT_DIM,
                          CHUNK_BYTES, fb + stage * 8, pol);
            }
        }

        if (++stage == NSTAGES) { stage = 0; parity ^= 1u; }
    }

    // One reduction per block.
#pragma unroll
    for (int o = 16; o; o >>= 1)
        total += __shfl_xor_sync(0xffffffffu, total, o);
    if (lane == 0) red[warp] = total;
    __syncthreads();

    if (warp == 0) {
        float v = (lane < WARPS_PER_BLOCK) ? red[lane] : 0.0f;
#pragma unroll
        for (int o = 8; o; o >>= 1)
            v += __shfl_xor_sync(0xffffffffu, v, o);
        if (lane == 0)
            atomicAdd(out, v * INV_FD_BATCH);
    }
}

extern "C" void kernel_launch(void* const* d_in, const int* in_sizes, int n_in,
                              void* d_out, int out_size) {
    const float* features = (const float*)d_in[0];
    const float* centers = (const float*)d_in[1];
    const long long* labels = (const long long*)d_in[2];
    float* out = (float*)d_out;

    cudaFuncSetAttribute(cl_main_kernel,
                         cudaFuncAttributeMaxDynamicSharedMemorySize,
                         NSTAGES * CHUNK_BYTES);

    cl_hist_kernel<<<NSLAB, HIST_THREADS>>>(labels, out);
    cl_main_kernel<<<MAIN_BLOCKS, THREADS, NSTAGES * CHUNK_BYTES>>>(features, centers, labels, out);
}